// round 13
// baseline (speedup 1.0000x reference)
#include <cuda_runtime.h>
#include <cuda_fp16.h>
#include <math.h>
#include <stdint.h>

#define DIM_H  128
#define DIM_3H 384
#define MAX_N  50000
#define MAX_E  600000
#define LN_EPS 1e-5f

// ---------------------------------------------------------------------------
// Scratch (device globals: allocation-free per harness rules)
// Replay-zero contracts: g_cnt is zero at entry (zero-init; re-zeroed by
// scan_kernel after consuming). g_colsum zero at entry (re-zeroed by gru_ln).
// ---------------------------------------------------------------------------
__device__ int    g_cnt[MAX_N];                          // in-degree histogram
__device__ int    g_rowptr[MAX_N + 1];                   // CSR row pointers
__device__ int    g_cur[MAX_N];                          // reorder cursors
__device__ int    g_csrc[MAX_E];                         // CSR src indices

__device__ __align__(256) __half g_S[MAX_N * DIM_H];     // sum of nodes[src]
__device__ float  g_deg[MAX_N];                          // in-degree (float)
__device__ float  g_colsum[DIM_H];
__device__ float  g_bias2[DIM_3H];            // b_ih + w_ih @ mean(nodes)
__device__ float  g_bm2[DIM_3H];              // w_ih @ b_msg

__device__ __align__(256) __half g_msg[MAX_N * DIM_H];   // messages (fp16)
__device__ __align__(256) __half g_ghh[MAX_N * DIM_3H];  // gh (fp16)
__device__ __align__(256) __half g_gih[MAX_N * DIM_3H];  // gi (fp16)

__device__ __align__(256) __half g_nh[MAX_N * DIM_H];    // nodes fp16
__device__ __align__(256) __half g_Wcat[512 * DIM_H];    // [W_msg; Wc2] fp16
__device__ __align__(256) __half g_Whh[DIM_3H * DIM_H];  // w_hh fp16

// ---------------------------------------------------------------------------
// PTX helpers (arch-neutral sm_80+/sm_90)
// ---------------------------------------------------------------------------
__device__ __forceinline__ uint32_t smem_u32(const void* p) {
    uint32_t a;
    asm("{ .reg .u64 t; cvta.to.shared.u64 t, %1; cvt.u32.u64 %0, t; }"
        : "=r"(a) : "l"(p));
    return a;
}

__device__ __forceinline__ void ldsm_x4(uint32_t& r0, uint32_t& r1,
                                        uint32_t& r2, uint32_t& r3,
                                        uint32_t addr) {
    asm volatile("ldmatrix.sync.aligned.m8n8.x4.shared.b16 {%0,%1,%2,%3}, [%4];"
                 : "=r"(r0), "=r"(r1), "=r"(r2), "=r"(r3) : "r"(addr));
}

__device__ __forceinline__ void mma_f16(float* d, uint32_t a0, uint32_t a1,
                                        uint32_t a2, uint32_t a3,
                                        uint32_t b0, uint32_t b1) {
    asm volatile(
        "mma.sync.aligned.m16n8k16.row.col.f32.f16.f16.f32 "
        "{%0,%1,%2,%3}, {%4,%5,%6,%7}, {%8,%9}, {%0,%1,%2,%3};"
        : "+f"(d[0]), "+f"(d[1]), "+f"(d[2]), "+f"(d[3])
        : "r"(a0), "r"(a1), "r"(a2), "r"(a3), "r"(b0), "r"(b1));
}

#define CP_ASYNC16(dst, src, sz)                                               \
    asm volatile("cp.async.cg.shared.global [%0], [%1], 16, %2;"               \
                 :: "r"(dst), "l"(src), "r"(sz) : "memory")
#define CP_COMMIT() asm volatile("cp.async.commit_group;" ::: "memory")
#define CP_WAIT0()  asm volatile("cp.async.wait_group 0;" ::: "memory")
#define CP_WAIT1()  asm volatile("cp.async.wait_group 1;" ::: "memory")

// 4 halfs -> 4 floats
__device__ __forceinline__ void ld4h(const __half* p, float* o) {
    uint2 u = *reinterpret_cast<const uint2*>(p);
    __half2 a = *reinterpret_cast<__half2*>(&u.x);
    __half2 b = *reinterpret_cast<__half2*>(&u.y);
    float2 fa = __half22float2(a), fb = __half22float2(b);
    o[0] = fa.x; o[1] = fa.y; o[2] = fb.x; o[3] = fb.y;
}

// ---------------------------------------------------------------------------
// Fused prep kernel. Blocks [0, nbN): nodes fp32->fp16 + colsum atomics.
// Blocks [nbN, nbN+32): W_msg -> Wcat rows 0..127, w_hh -> Whh.
// ---------------------------------------------------------------------------
__global__ void prep_kernel(const float* __restrict__ nodes,
                            const float* __restrict__ W_msg,
                            const float* __restrict__ w_hh,
                            int n8, int nbN) {
    int tid = threadIdx.x;
    if ((int)blockIdx.x >= nbN) {
        int i = (blockIdx.x - nbN) * 256 + tid;
        const float* src;
        __half* dst;
        int j;
        if (i < 2048)      { src = W_msg; dst = g_Wcat; j = i; }
        else if (i < 8192) { src = w_hh;  dst = g_Whh;  j = i - 2048; }
        else return;
        float4 v0 = reinterpret_cast<const float4*>(src)[j * 2];
        float4 v1 = reinterpret_cast<const float4*>(src)[j * 2 + 1];
        float xs[8] = {v0.x, v0.y, v0.z, v0.w, v1.x, v1.y, v1.z, v1.w};
        uint32_t hb[8];
#pragma unroll
        for (int t = 0; t < 8; t++)
            hb[t] = (uint32_t)__half_as_ushort(__float2half_rn(xs[t]));
        reinterpret_cast<uint4*>(dst)[j] =
            make_uint4(hb[0] | (hb[1] << 16), hb[2] | (hb[3] << 16),
                       hb[4] | (hb[5] << 16), hb[6] | (hb[7] << 16));
        return;
    }
    __shared__ float cs[DIM_H];
    if (tid < DIM_H) cs[tid] = 0.f;
    __syncthreads();
    int i = blockIdx.x * 256 + tid;
    int lane = tid & 31;
    float xs[8] = {0.f, 0.f, 0.f, 0.f, 0.f, 0.f, 0.f, 0.f};
    if (i < n8) {
        float4 v0 = reinterpret_cast<const float4*>(nodes)[i * 2];
        float4 v1 = reinterpret_cast<const float4*>(nodes)[i * 2 + 1];
        xs[0] = v0.x; xs[1] = v0.y; xs[2] = v0.z; xs[3] = v0.w;
        xs[4] = v1.x; xs[5] = v1.y; xs[6] = v1.z; xs[7] = v1.w;
        uint32_t hb[8];
#pragma unroll
        for (int t = 0; t < 8; t++)
            hb[t] = (uint32_t)__half_as_ushort(__float2half_rn(xs[t]));
        reinterpret_cast<uint4*>(g_nh)[i] =
            make_uint4(hb[0] | (hb[1] << 16), hb[2] | (hb[3] << 16),
                       hb[4] | (hb[5] << 16), hb[6] | (hb[7] << 16));
    }
#pragma unroll
    for (int t = 0; t < 8; t++)
        xs[t] += __shfl_down_sync(0xFFFFFFFF, xs[t], 16);
    if (lane < 16) {
        int c0 = lane * 8;
#pragma unroll
        for (int t = 0; t < 8; t++) atomicAdd(&cs[c0 + t], xs[t]);
    }
    __syncthreads();
    if (tid < DIM_H) atomicAdd(&g_colsum[tid], cs[tid]);
}

// ---------------------------------------------------------------------------
// Wc2 = w_ih @ W_msg  (fp32 compute, fp16 store into g_Wcat rows 128..511).
// ---------------------------------------------------------------------------
__global__ void wprod_kernel(const float* __restrict__ w_ih,
                             const float* __restrict__ W_msg) {
    __shared__ float wr[DIM_H];
    int j = blockIdx.x;
    int k = threadIdx.x;
    wr[k] = w_ih[(size_t)j * DIM_H + k];
    __syncthreads();
    float acc = 0.f;
#pragma unroll 8
    for (int c = 0; c < DIM_H; c++)
        acc = fmaf(wr[c], W_msg[(size_t)c * DIM_H + k], acc);
    g_Wcat[(size_t)(128 + j) * DIM_H + k] = __float2half_rn(acc);
}

// ---------------------------------------------------------------------------
// CSR build: histogram -> single-block scan -> reorder.
// ---------------------------------------------------------------------------
__global__ void hist_kernel(const int* __restrict__ edst, int n_edges) {
    int e = blockIdx.x * blockDim.x + threadIdx.x;
    if (e < n_edges) atomicAdd(&g_cnt[edst[e]], 1);
}

// Single block, 1024 threads. Exclusive scan of g_cnt[0..n) -> g_rowptr,
// g_cur; re-zeroes g_cnt for the next replay.
__global__ void scan_kernel(int n, int n_edges) {
    __shared__ int part[1024];
    int t = threadIdx.x;
    int c = (n + 1023) / 1024;
    int lo = t * c, hi = min(lo + c, n);
    int sum = 0;
    for (int i = lo; i < hi; i++) sum += g_cnt[i];
    part[t] = sum;
    __syncthreads();
    // Hillis-Steele inclusive scan over part[1024]
    for (int off = 1; off < 1024; off <<= 1) {
        int v = (t >= off) ? part[t - off] : 0;
        __syncthreads();
        if (t >= off) part[t] += v;
        __syncthreads();
    }
    int run = part[t] - sum;  // exclusive prefix of this chunk
    for (int i = lo; i < hi; i++) {
        int cv = g_cnt[i];
        g_rowptr[i] = run;
        g_cur[i] = run;
        g_cnt[i] = 0;          // re-zero for next replay
        run += cv;
    }
    if (t == 1023) g_rowptr[n] = n_edges;
}

__global__ void reorder_kernel(const int* __restrict__ esrc,
                               const int* __restrict__ edst, int n_edges) {
    int e = blockIdx.x * blockDim.x + threadIdx.x;
    if (e >= n_edges) return;
    int pos = atomicAdd(&g_cur[edst[e]], 1);
    g_csrc[pos] = esrc[e];
}

// ---------------------------------------------------------------------------
// Gather: one warp per node. S[i] = sum_{e in CSR row i} nh[src(e)] (fp32
// accumulate, single fp16 round). Also writes deg[i].
// ---------------------------------------------------------------------------
__global__ void gather_kernel(int n_nodes) {
    int gwarp = (blockIdx.x * blockDim.x + threadIdx.x) >> 5;
    int lane = threadIdx.x & 31;
    if (gwarp >= n_nodes) return;
    int r0 = g_rowptr[gwarp];
    int r1 = g_rowptr[gwarp + 1];
    float acc[4] = {0.f, 0.f, 0.f, 0.f};
    for (int base = r0; base < r1; base += 32) {
        int s = (base + lane < r1) ? g_csrc[base + lane] : 0;
        int m = min(32, r1 - base);
        for (int j = 0; j < m; j++) {
            int sj = __shfl_sync(0xFFFFFFFF, s, j);
            uint2 u = *reinterpret_cast<const uint2*>(
                g_nh + (size_t)sj * DIM_H + lane * 4);
            __half2 h0 = *reinterpret_cast<__half2*>(&u.x);
            __half2 h1 = *reinterpret_cast<__half2*>(&u.y);
            float2 f0 = __half22float2(h0), f1 = __half22float2(h1);
            acc[0] += f0.x; acc[1] += f0.y; acc[2] += f1.x; acc[3] += f1.y;
        }
    }
    if (lane == 0) g_deg[gwarp] = (float)(r1 - r0);
    __half2 o0 = __floats2half2_rn(acc[0], acc[1]);
    __half2 o1 = __floats2half2_rn(acc[2], acc[3]);
    uint2 ov = make_uint2(*reinterpret_cast<uint32_t*>(&o0),
                          *reinterpret_cast<uint32_t*>(&o1));
    *reinterpret_cast<uint2*>(g_S + (size_t)gwarp * DIM_H + lane * 4) = ov;
}

// ---------------------------------------------------------------------------
// bias2 = b_ih + w_ih @ (colsum/n); bm2 = w_ih @ b_msg. One warp per row.
// ---------------------------------------------------------------------------
__global__ void bias2bm_kernel(const float* __restrict__ w_ih,
                               const float* __restrict__ b_ih,
                               const float* __restrict__ b_msg, int n_nodes) {
    __shared__ float mean_s[DIM_H];
    __shared__ float bm_s[DIM_H];
    int tid = threadIdx.x;
    if (tid < DIM_H) {
        mean_s[tid] = g_colsum[tid] * (1.0f / (float)n_nodes);
        bm_s[tid] = b_msg[tid];
    }
    __syncthreads();
    int r = (blockIdx.x * blockDim.x + tid) >> 5;
    int lane = tid & 31;
    if (r >= DIM_3H) return;
    float acc = 0.f, acb = 0.f;
#pragma unroll
    for (int j = 0; j < 4; j++) {
        int k = lane + j * 32;
        float w = w_ih[(size_t)r * DIM_H + k];
        acc = fmaf(w, mean_s[k], acc);
        acb = fmaf(w, bm_s[k], acb);
    }
#pragma unroll
    for (int off = 16; off > 0; off >>= 1) {
        acc += __shfl_xor_sync(0xFFFFFFFF, acc, off);
        acb += __shfl_xor_sync(0xFFFFFFFF, acb, off);
    }
    if (lane == 0) {
        g_bias2[r] = acc + b_ih[r];
        g_bm2[r] = acb;
    }
}

// ---------------------------------------------------------------------------
// Weight-stationary tensor-core GEMM (single fp16 product, fp32 accum).
// Epilogue: C = acc + bias[col] + deg[row]*bvec[col]  (deg/bvec optional).
// ---------------------------------------------------------------------------
#define LDA 136
#define TILE_B (128 * LDA * 2)
#define SM_B    0
#define SM_A0   TILE_B
#define SM_A1   (2 * TILE_B)
#define SM_BIAS (3 * TILE_B)
#define SM_TOTAL (SM_BIAS + 1024)

__device__ __forceinline__ void cp_tile(uint32_t sdst, const __half* gsrc,
                                        int rows_valid) {
    int tid = threadIdx.x;
#pragma unroll
    for (int i = 0; i < 4; i++) {
        int idx = tid + i * 512;
        int r = idx >> 4, c = idx & 15;
        uint32_t d = sdst + (uint32_t)(r * LDA + c * 8) * 2;
        int ok = (r < rows_valid);
        const __half* s = gsrc + (size_t)(ok ? r : 0) * DIM_H + c * 8;
        CP_ASYNC16(d, s, ok ? 16 : 0);
    }
}

__global__ void __launch_bounds__(512, 1)
gemm_ws(const __half* __restrict__ A,
        const __half* __restrict__ B,
        const float* __restrict__ bias0,
        const float* __restrict__ bias1,
        const float* __restrict__ bvec0,
        const float* __restrict__ bvec1,
        const float* __restrict__ deg,
        __half* __restrict__ C0, int ldc0,
        __half* __restrict__ C1, int ldc1,
        int n_rows, int nrt, int nslices) {
    extern __shared__ char sm[];
    uint32_t smb = smem_u32(sm);
    const int tid = threadIdx.x;
    const int wid = tid >> 5;
    const int lane = tid & 31;
    const int ct = blockIdx.x;
    const int slice = blockIdx.y;

    const uint32_t bufA[2] = {SM_A0, SM_A1};

    cp_tile(smb + SM_B, B + (size_t)ct * 128 * DIM_H, 128);
    cp_tile(smb + bufA[0], A + (size_t)slice * 128 * DIM_H,
            n_rows - slice * 128);
    CP_COMMIT();

    float* bias_s = reinterpret_cast<float*>(sm + SM_BIAS);
    if (tid < 128) {
        const float* bp = (ct == 0) ? bias0 : bias1;
        const float* vp = (ct == 0) ? bvec0 : bvec1;
        int off = (ct == 0) ? tid : (ct - 1) * 128 + tid;
        bias_s[tid] = bp ? bp[off] : 0.f;
        bias_s[128 + tid] = vp ? vp[off] : 0.f;
    }

    const int wr = wid & 7;
    const int wc = wid >> 3;

    const int a_m = lane & 15;
    const int a_k = (lane >> 4) * 8;
    const uint32_t offA = (uint32_t)(((wr * 16 + a_m) * LDA + a_k) * 2);

    const int b_n = (lane & 7) + (lane >> 4) * 8;
    const int b_k = ((lane >> 3) & 1) * 8;
    uint32_t offB[4];
#pragma unroll
    for (int p = 0; p < 4; p++)
        offB[p] = (uint32_t)(((wc * 64 + p * 16 + b_n) * LDA + b_k) * 2);

    const int r_in = lane >> 2;
    const int c_in = (lane & 3) * 2;

    __half* Cp;
    int ldc, colbase;
    if (ct == 0) { Cp = C0; ldc = ldc0; colbase = 0; }
    else         { Cp = C1; ldc = ldc1; colbase = (ct - 1) * 128; }

    int nbuf = 0;
    for (int it = slice; it < nrt; it += nslices) {
        int next = it + nslices;
        __syncthreads();
        if (next < nrt) {
            cp_tile(smb + bufA[nbuf ^ 1], A + (size_t)next * 128 * DIM_H,
                    n_rows - next * 128);
            CP_COMMIT();
            CP_WAIT1();
        } else {
            CP_WAIT0();
        }
        __syncthreads();

        const uint32_t a_b = smb + bufA[nbuf];

        float acc[8][4];
#pragma unroll
        for (int nt = 0; nt < 8; nt++)
#pragma unroll
            for (int e = 0; e < 4; e++) acc[nt][e] = 0.f;

#pragma unroll
        for (int ks = 0; ks < 8; ks++) {
            const uint32_t kb = ks * 32;
            uint32_t a0, a1, a2, a3;
            ldsm_x4(a0, a1, a2, a3, a_b + offA + kb);
#pragma unroll
            for (int p = 0; p < 4; p++) {
                uint32_t b0, b1, b2, b3;
                ldsm_x4(b0, b1, b2, b3, smb + SM_B + offB[p] + kb);
                mma_f16(acc[2 * p],     a0, a1, a2, a3, b0, b1);
                mma_f16(acc[2 * p + 1], a0, a1, a2, a3, b2, b3);
            }
        }

        const int row_a = it * 128 + wr * 16 + r_in;
        const int row_b = row_a + 8;
        float da = 0.f, db = 0.f;
        if (deg != nullptr) {
            if (row_a < n_rows) da = deg[row_a];
            if (row_b < n_rows) db = deg[row_b];
        }
#pragma unroll
        for (int nt = 0; nt < 8; nt++) {
            int cb = wc * 64 + nt * 8 + c_in;
            int cl = colbase + cb;
            float b0c = bias_s[cb],       b1c = bias_s[cb + 1];
            float v0c = bias_s[128 + cb], v1c = bias_s[128 + cb + 1];
            if (row_a < n_rows)
                *reinterpret_cast<__half2*>(Cp + (size_t)row_a * ldc + cl) =
                    __floats2half2_rn(acc[nt][0] + b0c + da * v0c,
                                      acc[nt][1] + b1c + da * v1c);
            if (row_b < n_rows)
                *reinterpret_cast<__half2*>(Cp + (size_t)row_b * ldc + cl) =
                    __floats2half2_rn(acc[nt][2] + b0c + db * v0c,
                                      acc[nt][3] + b1c + db * v1c);
        }
        nbuf ^= 1;
    }
}

// ---------------------------------------------------------------------------
// Fused GRU gates + LayerNorm + message residual. One warp per node.
// Re-zeroes g_colsum for the next graph replay (block 0).
// ---------------------------------------------------------------------------
__device__ __forceinline__ float sigmoidf_(float x) {
    return 1.0f / (1.0f + expf(-x));
}

__global__ void gru_ln_kernel(const float* __restrict__ nodes,
                              const float* __restrict__ gamma,
                              const float* __restrict__ beta,
                              float* __restrict__ out, int n_nodes) {
    if (blockIdx.x == 0 && threadIdx.x < DIM_H)
        g_colsum[threadIdx.x] = 0.f;

    int gwarp = (blockIdx.x * blockDim.x + threadIdx.x) >> 5;
    int lane  = threadIdx.x & 31;
    if (gwarp >= n_nodes) return;

    size_t base = (size_t)gwarp * DIM_H;
    size_t gb   = (size_t)gwarp * DIM_3H;
    int le = lane * 4;

    float4 h4 = reinterpret_cast<const float4*>(nodes + base)[lane];

    float mm[4], ir[4], iz[4], in_[4], hr[4], hz[4], hn[4];
    ld4h(g_msg + base + le, mm);
    ld4h(g_gih + gb + le, ir);
    ld4h(g_gih + gb + 128 + le, iz);
    ld4h(g_gih + gb + 256 + le, in_);
    ld4h(g_ghh + gb + le, hr);
    ld4h(g_ghh + gb + 128 + le, hz);
    ld4h(g_ghh + gb + 256 + le, hn);

    float hh[4] = {h4.x, h4.y, h4.z, h4.w};

    float hx[4];
    float s = 0.f, s2 = 0.f;
#pragma unroll
    for (int c = 0; c < 4; c++) {
        float r = sigmoidf_(ir[c] + hr[c]);
        float z = sigmoidf_(iz[c] + hz[c]);
        float n = tanhf(in_[c] + r * hn[c]);
        hx[c] = (1.0f - z) * n + z * hh[c];
        s  += hx[c];
        s2 += hx[c] * hx[c];
    }
#pragma unroll
    for (int off = 16; off > 0; off >>= 1) {
        s  += __shfl_xor_sync(0xFFFFFFFF, s,  off);
        s2 += __shfl_xor_sync(0xFFFFFFFF, s2, off);
    }
    float mu   = s  * (1.0f / DIM_H);
    float var  = s2 * (1.0f / DIM_H) - mu * mu;
    float rstd = rsqrtf(var + LN_EPS);

    float4 g4 = reinterpret_cast<const float4*>(gamma)[lane];
    float4 b4 = reinterpret_cast<const float4*>(beta)[lane];
    float gg[4] = {g4.x, g4.y, g4.z, g4.w};
    float bb[4] = {b4.x, b4.y, b4.z, b4.w};

    float o[4];
#pragma unroll
    for (int c = 0; c < 4; c++)
        o[c] = gg[c] * (hx[c] - mu) * rstd + bb[c] + mm[c];

    reinterpret_cast<float4*>(out + base)[lane] =
        make_float4(o[0], o[1], o[2], o[3]);
}

// ---------------------------------------------------------------------------
// Launch. Graph:
//   main: prep (evP) -> [wait evCSR] gather -> [wait evB] gemmMG
//         -> [wait evJoin] gru_ln
//   s2:   [wait evFork] wprod -> hist -> scan -> reorder (evCSR)
//         -> [wait evP] bias2bm (evB) -> gemmGH (evJoin)
// ---------------------------------------------------------------------------
extern "C" void kernel_launch(void* const* d_in, const int* in_sizes, int n_in,
                              void* d_out, int out_size) {
    const float* nodes = (const float*)d_in[0];
    const float* W_msg = (const float*)d_in[1];
    const float* b_msg = (const float*)d_in[2];
    const float* w_ih  = (const float*)d_in[3];
    const float* w_hh  = (const float*)d_in[4];
    const float* b_ih  = (const float*)d_in[5];
    const float* b_hh  = (const float*)d_in[6];
    const float* gamma = (const float*)d_in[7];
    const float* beta  = (const float*)d_in[8];
    const int*   esrc  = (const int*)d_in[9];
    const int*   edst  = (const int*)d_in[10];
    float* out = (float*)d_out;

    int n_nodes = in_sizes[0] / DIM_H;
    int n_edges = in_sizes[9];

    float *pBias2, *pBm2, *pDeg;
    __half *pS, *pMsg, *pGhh, *pGih, *pNh, *pWc, *pWhh;
    cudaGetSymbolAddress((void**)&pBias2, g_bias2);
    cudaGetSymbolAddress((void**)&pBm2, g_bm2);
    cudaGetSymbolAddress((void**)&pDeg, g_deg);
    cudaGetSymbolAddress((void**)&pS,   g_S);
    cudaGetSymbolAddress((void**)&pMsg, g_msg);
    cudaGetSymbolAddress((void**)&pGhh, g_ghh);
    cudaGetSymbolAddress((void**)&pGih, g_gih);
    cudaGetSymbolAddress((void**)&pNh,  g_nh);
    cudaGetSymbolAddress((void**)&pWc,  g_Wcat);
    cudaGetSymbolAddress((void**)&pWhh, g_Whh);

    cudaFuncSetAttribute(gemm_ws,
                         cudaFuncAttributeMaxDynamicSharedMemorySize, SM_TOTAL);

    static cudaStream_t s2 = nullptr;
    static cudaEvent_t evFork = nullptr, evP = nullptr, evCSR = nullptr,
                       evB = nullptr, evJoin = nullptr;
    if (s2 == nullptr) {
        cudaStreamCreateWithFlags(&s2, cudaStreamNonBlocking);
        cudaEventCreateWithFlags(&evFork, cudaEventDisableTiming);
        cudaEventCreateWithFlags(&evP, cudaEventDisableTiming);
        cudaEventCreateWithFlags(&evCSR, cudaEventDisableTiming);
        cudaEventCreateWithFlags(&evB, cudaEventDisableTiming);
        cudaEventCreateWithFlags(&evJoin, cudaEventDisableTiming);
    }

    int nrt = (n_nodes + 127) / 128;
    int n8 = n_nodes * DIM_H / 8;
    int nbN = (n8 + 255) / 256;
    int nbW = 32;

    // Side stream: weight product + CSR build (independent of prep)
    cudaEventRecord(evFork, 0);
    cudaStreamWaitEvent(s2, evFork, 0);
    wprod_kernel<<<DIM_3H, DIM_H, 0, s2>>>(w_ih, W_msg);
    hist_kernel<<<(n_edges + 255) / 256, 256, 0, s2>>>(edst, n_edges);
    scan_kernel<<<1, 1024, 0, s2>>>(n_nodes, n_edges);
    reorder_kernel<<<(n_edges + 255) / 256, 256, 0, s2>>>(esrc, edst, n_edges);
    cudaEventRecord(evCSR, s2);

    // Main: fused prep (nodes convert + colsum + weight converts)
    prep_kernel<<<nbN + nbW, 256>>>(nodes, W_msg, w_hh, n8, nbN);
    cudaEventRecord(evP, 0);

    // Side: bias2+bm2 (needs colsum), then gh gemm
    cudaStreamWaitEvent(s2, evP, 0);
    bias2bm_kernel<<<12, 1024, 0, s2>>>(w_ih, b_ih, b_msg, n_nodes);
    cudaEventRecord(evB, s2);
    gemm_ws<<<dim3(3, 49), 512, SM_TOTAL, s2>>>(
        pNh, pWhh, b_hh, b_hh + 128, nullptr, nullptr, nullptr,
        pGhh, DIM_3H, pGhh + 128, DIM_3H, n_nodes, nrt, 49);
    cudaEventRecord(evJoin, s2);

    // Main: gather S[i] = sum nh[src] over CSR row i (fp32 accum)
    cudaStreamWaitEvent(0, evCSR, 0);
    gather_kernel<<<(n_nodes * 32 + 255) / 256, 256>>>(n_nodes);

    // Main: [messages | gi] = S @ [W_msg; Wc2]^T + deg*bvec + bias
    cudaStreamWaitEvent(0, evB, 0);
    gemm_ws<<<dim3(4, 37), 512, SM_TOTAL>>>(
        pS, pWc, nullptr, pBias2, b_msg, pBm2, pDeg,
        pMsg, DIM_H, pGih, DIM_3H, n_nodes, nrt, 37);

    // Join: gru_ln needs gh from s2
    cudaStreamWaitEvent(0, evJoin, 0);
    gru_ln_kernel<<<(n_nodes + 7) / 8, 256>>>(nodes, gamma, beta, out, n_nodes);
}

// round 14
// speedup vs baseline: 1.3686x; 1.3686x over previous
#include <cuda_runtime.h>
#include <cuda_fp16.h>
#include <math.h>
#include <stdint.h>

#define DIM_H  128
#define DIM_3H 384
#define MAX_N  50000
#define MAX_E  600000
#define LN_EPS 1e-5f

// ---------------------------------------------------------------------------
// Scratch (device globals: allocation-free per harness rules)
// Replay-zero contracts: g_S/g_deg zero at entry (zero-init on load; re-zeroed
// by gru_ln each run). g_colsum zero at entry (re-zeroed by gru_ln).
// ---------------------------------------------------------------------------
__device__ __align__(256) __half g_S[MAX_N * DIM_H];     // sum of fp16(nodes[src])
__device__ float  g_deg[MAX_N];                          // in-degree (float)
__device__ float  g_colsum[DIM_H];
__device__ float  g_bias2[DIM_3H];            // b_ih + w_ih @ mean(nodes)
__device__ float  g_bm2[DIM_3H];              // w_ih @ b_msg

__device__ __align__(256) __half g_msg[MAX_N * DIM_H];   // messages (fp16)
__device__ __align__(256) __half g_ghh[MAX_N * DIM_3H];  // gh (fp16)
__device__ __align__(256) __half g_gih[MAX_N * DIM_3H];  // gi (fp16)

__device__ __align__(256) __half g_nh[MAX_N * DIM_H];    // nodes fp16
__device__ __align__(256) __half g_Wcat[512 * DIM_H];    // [W_msg; Wc2] fp16
__device__ __align__(256) __half g_Whh[DIM_3H * DIM_H];  // w_hh fp16

// ---------------------------------------------------------------------------
// PTX helpers (arch-neutral sm_80+/sm_90)
// ---------------------------------------------------------------------------
__device__ __forceinline__ uint32_t smem_u32(const void* p) {
    uint32_t a;
    asm("{ .reg .u64 t; cvta.to.shared.u64 t, %1; cvt.u32.u64 %0, t; }"
        : "=r"(a) : "l"(p));
    return a;
}

__device__ __forceinline__ void ldsm_x4(uint32_t& r0, uint32_t& r1,
                                        uint32_t& r2, uint32_t& r3,
                                        uint32_t addr) {
    asm volatile("ldmatrix.sync.aligned.m8n8.x4.shared.b16 {%0,%1,%2,%3}, [%4];"
                 : "=r"(r0), "=r"(r1), "=r"(r2), "=r"(r3) : "r"(addr));
}

__device__ __forceinline__ void mma_f16(float* d, uint32_t a0, uint32_t a1,
                                        uint32_t a2, uint32_t a3,
                                        uint32_t b0, uint32_t b1) {
    asm volatile(
        "mma.sync.aligned.m16n8k16.row.col.f32.f16.f16.f32 "
        "{%0,%1,%2,%3}, {%4,%5,%6,%7}, {%8,%9}, {%0,%1,%2,%3};"
        : "+f"(d[0]), "+f"(d[1]), "+f"(d[2]), "+f"(d[3])
        : "r"(a0), "r"(a1), "r"(a2), "r"(a3), "r"(b0), "r"(b1));
}

#define CP_ASYNC16(dst, src, sz)                                               \
    asm volatile("cp.async.cg.shared.global [%0], [%1], 16, %2;"               \
                 :: "r"(dst), "l"(src), "r"(sz) : "memory")
#define CP_COMMIT() asm volatile("cp.async.commit_group;" ::: "memory")
#define CP_WAIT0()  asm volatile("cp.async.wait_group 0;" ::: "memory")
#define CP_WAIT1()  asm volatile("cp.async.wait_group 1;" ::: "memory")

// 4 halfs -> 4 floats
__device__ __forceinline__ void ld4h(const __half* p, float* o) {
    uint2 u = *reinterpret_cast<const uint2*>(p);
    __half2 a = *reinterpret_cast<__half2*>(&u.x);
    __half2 b = *reinterpret_cast<__half2*>(&u.y);
    float2 fa = __half22float2(a), fb = __half22float2(b);
    o[0] = fa.x; o[1] = fa.y; o[2] = fb.x; o[3] = fb.y;
}

// ---------------------------------------------------------------------------
// Fused prep kernel. Blocks [0, nbN): nodes fp32->fp16 + colsum atomics.
// Blocks [nbN, nbN+32): W_msg -> Wcat rows 0..127, w_hh -> Whh.
// ---------------------------------------------------------------------------
__global__ void prep_kernel(const float* __restrict__ nodes,
                            const float* __restrict__ W_msg,
                            const float* __restrict__ w_hh,
                            int n8, int nbN) {
    int tid = threadIdx.x;
    if ((int)blockIdx.x >= nbN) {
        int i = (blockIdx.x - nbN) * 256 + tid;
        const float* src;
        __half* dst;
        int j;
        if (i < 2048)      { src = W_msg; dst = g_Wcat; j = i; }
        else if (i < 8192) { src = w_hh;  dst = g_Whh;  j = i - 2048; }
        else return;
        float4 v0 = reinterpret_cast<const float4*>(src)[j * 2];
        float4 v1 = reinterpret_cast<const float4*>(src)[j * 2 + 1];
        float xs[8] = {v0.x, v0.y, v0.z, v0.w, v1.x, v1.y, v1.z, v1.w};
        uint32_t hb[8];
#pragma unroll
        for (int t = 0; t < 8; t++)
            hb[t] = (uint32_t)__half_as_ushort(__float2half_rn(xs[t]));
        reinterpret_cast<uint4*>(dst)[j] =
            make_uint4(hb[0] | (hb[1] << 16), hb[2] | (hb[3] << 16),
                       hb[4] | (hb[5] << 16), hb[6] | (hb[7] << 16));
        return;
    }
    __shared__ float cs[DIM_H];
    if (tid < DIM_H) cs[tid] = 0.f;
    __syncthreads();
    int i = blockIdx.x * 256 + tid;
    int lane = tid & 31;
    float xs[8] = {0.f, 0.f, 0.f, 0.f, 0.f, 0.f, 0.f, 0.f};
    if (i < n8) {
        float4 v0 = reinterpret_cast<const float4*>(nodes)[i * 2];
        float4 v1 = reinterpret_cast<const float4*>(nodes)[i * 2 + 1];
        xs[0] = v0.x; xs[1] = v0.y; xs[2] = v0.z; xs[3] = v0.w;
        xs[4] = v1.x; xs[5] = v1.y; xs[6] = v1.z; xs[7] = v1.w;
        uint32_t hb[8];
#pragma unroll
        for (int t = 0; t < 8; t++)
            hb[t] = (uint32_t)__half_as_ushort(__float2half_rn(xs[t]));
        reinterpret_cast<uint4*>(g_nh)[i] =
            make_uint4(hb[0] | (hb[1] << 16), hb[2] | (hb[3] << 16),
                       hb[4] | (hb[5] << 16), hb[6] | (hb[7] << 16));
    }
#pragma unroll
    for (int t = 0; t < 8; t++)
        xs[t] += __shfl_down_sync(0xFFFFFFFF, xs[t], 16);
    if (lane < 16) {
        int c0 = lane * 8;
#pragma unroll
        for (int t = 0; t < 8; t++) atomicAdd(&cs[c0 + t], xs[t]);
    }
    __syncthreads();
    if (tid < DIM_H) atomicAdd(&g_colsum[tid], cs[tid]);
}

// ---------------------------------------------------------------------------
// Wc2 = w_ih @ W_msg  (fp32 compute, fp16 store into g_Wcat rows 128..511).
// ---------------------------------------------------------------------------
__global__ void wprod_kernel(const float* __restrict__ w_ih,
                             const float* __restrict__ W_msg) {
    __shared__ float wr[DIM_H];
    int j = blockIdx.x;
    int k = threadIdx.x;
    wr[k] = w_ih[(size_t)j * DIM_H + k];
    __syncthreads();
    float acc = 0.f;
#pragma unroll 8
    for (int c = 0; c < DIM_H; c++)
        acc = fmaf(wr[c], W_msg[(size_t)c * DIM_H + k], acc);
    g_Wcat[(size_t)(128 + j) * DIM_H + k] = __float2half_rn(acc);
}

// bias2 = b_ih + w_ih @ (colsum/n); bm2 = w_ih @ b_msg. One warp per row.
__global__ void bias2bm_kernel(const float* __restrict__ w_ih,
                               const float* __restrict__ b_ih,
                               const float* __restrict__ b_msg, int n_nodes) {
    __shared__ float mean_s[DIM_H];
    __shared__ float bm_s[DIM_H];
    int tid = threadIdx.x;
    if (tid < DIM_H) {
        mean_s[tid] = g_colsum[tid] * (1.0f / (float)n_nodes);
        bm_s[tid] = b_msg[tid];
    }
    __syncthreads();
    int r = (blockIdx.x * blockDim.x + tid) >> 5;
    int lane = tid & 31;
    if (r >= DIM_3H) return;
    float acc = 0.f, acb = 0.f;
#pragma unroll
    for (int j = 0; j < 4; j++) {
        int k = lane + j * 32;
        float w = w_ih[(size_t)r * DIM_H + k];
        acc = fmaf(w, mean_s[k], acc);
        acb = fmaf(w, bm_s[k], acb);
    }
#pragma unroll
    for (int off = 16; off > 0; off >>= 1) {
        acc += __shfl_xor_sync(0xFFFFFFFF, acc, off);
        acb += __shfl_xor_sync(0xFFFFFFFF, acb, off);
    }
    if (lane == 0) {
        g_bias2[r] = acc + b_ih[r];
        g_bm2[r] = acb;
    }
}

// ---------------------------------------------------------------------------
// Weight-stationary tensor-core GEMM (single fp16 product, fp32 accum).
// Epilogue: C = acc + bias[col] + deg[row]*bvec[col]  (deg/bvec optional).
// ---------------------------------------------------------------------------
#define LDA 136
#define TILE_B (128 * LDA * 2)
#define SM_B    0
#define SM_A0   TILE_B
#define SM_A1   (2 * TILE_B)
#define SM_BIAS (3 * TILE_B)
#define SM_TOTAL (SM_BIAS + 1024)

__device__ __forceinline__ void cp_tile(uint32_t sdst, const __half* gsrc,
                                        int rows_valid) {
    int tid = threadIdx.x;
#pragma unroll
    for (int i = 0; i < 4; i++) {
        int idx = tid + i * 512;
        int r = idx >> 4, c = idx & 15;
        uint32_t d = sdst + (uint32_t)(r * LDA + c * 8) * 2;
        int ok = (r < rows_valid);
        const __half* s = gsrc + (size_t)(ok ? r : 0) * DIM_H + c * 8;
        CP_ASYNC16(d, s, ok ? 16 : 0);
    }
}

__global__ void __launch_bounds__(512, 1)
gemm_ws(const __half* __restrict__ A,
        const __half* __restrict__ B,
        const float* __restrict__ bias0,
        const float* __restrict__ bias1,
        const float* __restrict__ bvec0,
        const float* __restrict__ bvec1,
        const float* __restrict__ deg,
        __half* __restrict__ C0, int ldc0,
        __half* __restrict__ C1, int ldc1,
        int n_rows, int nrt, int nslices) {
    extern __shared__ char sm[];
    uint32_t smb = smem_u32(sm);
    const int tid = threadIdx.x;
    const int wid = tid >> 5;
    const int lane = tid & 31;
    const int ct = blockIdx.x;
    const int slice = blockIdx.y;

    const uint32_t bufA[2] = {SM_A0, SM_A1};

    cp_tile(smb + SM_B, B + (size_t)ct * 128 * DIM_H, 128);
    cp_tile(smb + bufA[0], A + (size_t)slice * 128 * DIM_H,
            n_rows - slice * 128);
    CP_COMMIT();

    float* bias_s = reinterpret_cast<float*>(sm + SM_BIAS);
    if (tid < 128) {
        const float* bp = (ct == 0) ? bias0 : bias1;
        const float* vp = (ct == 0) ? bvec0 : bvec1;
        int off = (ct == 0) ? tid : (ct - 1) * 128 + tid;
        bias_s[tid] = bp ? bp[off] : 0.f;
        bias_s[128 + tid] = vp ? vp[off] : 0.f;
    }

    const int wr = wid & 7;
    const int wc = wid >> 3;

    const int a_m = lane & 15;
    const int a_k = (lane >> 4) * 8;
    const uint32_t offA = (uint32_t)(((wr * 16 + a_m) * LDA + a_k) * 2);

    const int b_n = (lane & 7) + (lane >> 4) * 8;
    const int b_k = ((lane >> 3) & 1) * 8;
    uint32_t offB[4];
#pragma unroll
    for (int p = 0; p < 4; p++)
        offB[p] = (uint32_t)(((wc * 64 + p * 16 + b_n) * LDA + b_k) * 2);

    const int r_in = lane >> 2;
    const int c_in = (lane & 3) * 2;

    __half* Cp;
    int ldc, colbase;
    if (ct == 0) { Cp = C0; ldc = ldc0; colbase = 0; }
    else         { Cp = C1; ldc = ldc1; colbase = (ct - 1) * 128; }

    int nbuf = 0;
    for (int it = slice; it < nrt; it += nslices) {
        int next = it + nslices;
        __syncthreads();
        if (next < nrt) {
            cp_tile(smb + bufA[nbuf ^ 1], A + (size_t)next * 128 * DIM_H,
                    n_rows - next * 128);
            CP_COMMIT();
            CP_WAIT1();
        } else {
            CP_WAIT0();
        }
        __syncthreads();

        const uint32_t a_b = smb + bufA[nbuf];

        float acc[8][4];
#pragma unroll
        for (int nt = 0; nt < 8; nt++)
#pragma unroll
            for (int e = 0; e < 4; e++) acc[nt][e] = 0.f;

#pragma unroll
        for (int ks = 0; ks < 8; ks++) {
            const uint32_t kb = ks * 32;
            uint32_t a0, a1, a2, a3;
            ldsm_x4(a0, a1, a2, a3, a_b + offA + kb);
#pragma unroll
            for (int p = 0; p < 4; p++) {
                uint32_t b0, b1, b2, b3;
                ldsm_x4(b0, b1, b2, b3, smb + SM_B + offB[p] + kb);
                mma_f16(acc[2 * p],     a0, a1, a2, a3, b0, b1);
                mma_f16(acc[2 * p + 1], a0, a1, a2, a3, b2, b3);
            }
        }

        const int row_a = it * 128 + wr * 16 + r_in;
        const int row_b = row_a + 8;
        float da = 0.f, db = 0.f;
        if (deg != nullptr) {
            if (row_a < n_rows) da = deg[row_a];
            if (row_b < n_rows) db = deg[row_b];
        }
#pragma unroll
        for (int nt = 0; nt < 8; nt++) {
            int cb = wc * 64 + nt * 8 + c_in;
            int cl = colbase + cb;
            float b0c = bias_s[cb],       b1c = bias_s[cb + 1];
            float v0c = bias_s[128 + cb], v1c = bias_s[128 + cb + 1];
            if (row_a < n_rows)
                *reinterpret_cast<__half2*>(Cp + (size_t)row_a * ldc + cl) =
                    __floats2half2_rn(acc[nt][0] + b0c + da * v0c,
                                      acc[nt][1] + b1c + da * v1c);
            if (row_b < n_rows)
                *reinterpret_cast<__half2*>(Cp + (size_t)row_b * ldc + cl) =
                    __floats2half2_rn(acc[nt][2] + b0c + db * v0c,
                                      acc[nt][3] + b1c + db * v1c);
        }
        nbuf ^= 1;
    }
}

// ---------------------------------------------------------------------------
// Edge scatter: TWO edges per warp (16 lanes each, 16B per lane).
// Reads fp32 nodes directly (no prep dependency!), converts to fp16 in-reg
// (identical values to scattering nh), red.global.add.noftz.v4.f16x2.
// ---------------------------------------------------------------------------
__global__ void scatter_kernel(const int* __restrict__ esrc,
                               const int* __restrict__ edst,
                               const float* __restrict__ nodes, int n_edges) {
    int gwarp = (blockIdx.x * blockDim.x + threadIdx.x) >> 5;
    int lane  = threadIdx.x & 31;
    int e = gwarp * 2 + (lane >> 4);
    int hl = lane & 15;
    if (e >= n_edges) return;
    int s = esrc[e];
    int d = edst[e];
    const float4* np =
        reinterpret_cast<const float4*>(nodes + (size_t)s * DIM_H + hl * 8);
    float4 v0 = np[0], v1 = np[1];
    __half2 h0 = __floats2half2_rn(v0.x, v0.y);
    __half2 h1 = __floats2half2_rn(v0.z, v0.w);
    __half2 h2 = __floats2half2_rn(v1.x, v1.y);
    __half2 h3 = __floats2half2_rn(v1.z, v1.w);
    __half* p = g_S + (size_t)d * DIM_H + hl * 8;
    asm volatile("red.global.add.noftz.v4.f16x2 [%0], {%1, %2, %3, %4};"
                 :: "l"(p),
                    "r"(*reinterpret_cast<uint32_t*>(&h0)),
                    "r"(*reinterpret_cast<uint32_t*>(&h1)),
                    "r"(*reinterpret_cast<uint32_t*>(&h2)),
                    "r"(*reinterpret_cast<uint32_t*>(&h3))
                 : "memory");
    if (hl == 0) atomicAdd(&g_deg[d], 1.0f);
}

// ---------------------------------------------------------------------------
// Fused GRU gates + LayerNorm + message residual. One warp per node.
// Re-zeroes g_colsum (block 0) and this node's S row + deg for next replay.
// ---------------------------------------------------------------------------
__device__ __forceinline__ float sigmoidf_(float x) {
    return 1.0f / (1.0f + expf(-x));
}

__global__ void gru_ln_kernel(const float* __restrict__ nodes,
                              const float* __restrict__ gamma,
                              const float* __restrict__ beta,
                              float* __restrict__ out, int n_nodes) {
    if (blockIdx.x == 0 && threadIdx.x < DIM_H)
        g_colsum[threadIdx.x] = 0.f;

    int gwarp = (blockIdx.x * blockDim.x + threadIdx.x) >> 5;
    int lane  = threadIdx.x & 31;
    if (gwarp >= n_nodes) return;

    size_t base = (size_t)gwarp * DIM_H;
    size_t gb   = (size_t)gwarp * DIM_3H;
    int le = lane * 4;

    float4 h4 = reinterpret_cast<const float4*>(nodes + base)[lane];

    float mm[4], ir[4], iz[4], in_[4], hr[4], hz[4], hn[4];
    ld4h(g_msg + base + le, mm);
    ld4h(g_gih + gb + le, ir);
    ld4h(g_gih + gb + 128 + le, iz);
    ld4h(g_gih + gb + 256 + le, in_);
    ld4h(g_ghh + gb + le, hr);
    ld4h(g_ghh + gb + 128 + le, hz);
    ld4h(g_ghh + gb + 256 + le, hn);

    // Re-zero S row + deg for the next graph replay (S was consumed by gemmMG)
    reinterpret_cast<uint2*>(g_S + base)[lane] = make_uint2(0, 0);
    if (lane == 0) g_deg[gwarp] = 0.f;

    float hh[4] = {h4.x, h4.y, h4.z, h4.w};

    float hx[4];
    float s = 0.f, s2 = 0.f;
#pragma unroll
    for (int c = 0; c < 4; c++) {
        float r = sigmoidf_(ir[c] + hr[c]);
        float z = sigmoidf_(iz[c] + hz[c]);
        float n = tanhf(in_[c] + r * hn[c]);
        hx[c] = (1.0f - z) * n + z * hh[c];
        s  += hx[c];
        s2 += hx[c] * hx[c];
    }
#pragma unroll
    for (int off = 16; off > 0; off >>= 1) {
        s  += __shfl_xor_sync(0xFFFFFFFF, s,  off);
        s2 += __shfl_xor_sync(0xFFFFFFFF, s2, off);
    }
    float mu   = s  * (1.0f / DIM_H);
    float var  = s2 * (1.0f / DIM_H) - mu * mu;
    float rstd = rsqrtf(var + LN_EPS);

    float4 g4 = reinterpret_cast<const float4*>(gamma)[lane];
    float4 b4 = reinterpret_cast<const float4*>(beta)[lane];
    float gg[4] = {g4.x, g4.y, g4.z, g4.w};
    float bb[4] = {b4.x, b4.y, b4.z, b4.w};

    float o[4];
#pragma unroll
    for (int c = 0; c < 4; c++)
        o[c] = gg[c] * (hx[c] - mu) * rstd + bb[c] + mm[c];

    reinterpret_cast<float4*>(out + base)[lane] =
        make_float4(o[0], o[1], o[2], o[3]);
}

// ---------------------------------------------------------------------------
// Launch. Graph:
//   main: scatter (evSc) -> [wait evB] gemmMG -> [wait evJoin] gru_ln
//   s2:   [wait evFork] wprod -> prep -> bias2bm (evB)
//         -> [wait evSc] gemmGH (evJoin)     (gemmGH runs concurrent w/ gemmMG)
// ---------------------------------------------------------------------------
extern "C" void kernel_launch(void* const* d_in, const int* in_sizes, int n_in,
                              void* d_out, int out_size) {
    const float* nodes = (const float*)d_in[0];
    const float* W_msg = (const float*)d_in[1];
    const float* b_msg = (const float*)d_in[2];
    const float* w_ih  = (const float*)d_in[3];
    const float* w_hh  = (const float*)d_in[4];
    const float* b_ih  = (const float*)d_in[5];
    const float* b_hh  = (const float*)d_in[6];
    const float* gamma = (const float*)d_in[7];
    const float* beta  = (const float*)d_in[8];
    const int*   esrc  = (const int*)d_in[9];
    const int*   edst  = (const int*)d_in[10];
    float* out = (float*)d_out;

    int n_nodes = in_sizes[0] / DIM_H;
    int n_edges = in_sizes[9];

    float *pBias2, *pBm2, *pDeg;
    __half *pS, *pMsg, *pGhh, *pGih, *pNh, *pWc, *pWhh;
    cudaGetSymbolAddress((void**)&pBias2, g_bias2);
    cudaGetSymbolAddress((void**)&pBm2, g_bm2);
    cudaGetSymbolAddress((void**)&pDeg, g_deg);
    cudaGetSymbolAddress((void**)&pS,   g_S);
    cudaGetSymbolAddress((void**)&pMsg, g_msg);
    cudaGetSymbolAddress((void**)&pGhh, g_ghh);
    cudaGetSymbolAddress((void**)&pGih, g_gih);
    cudaGetSymbolAddress((void**)&pNh,  g_nh);
    cudaGetSymbolAddress((void**)&pWc,  g_Wcat);
    cudaGetSymbolAddress((void**)&pWhh, g_Whh);

    cudaFuncSetAttribute(gemm_ws,
                         cudaFuncAttributeMaxDynamicSharedMemorySize, SM_TOTAL);

    static cudaStream_t s2 = nullptr;
    static cudaEvent_t evFork = nullptr, evSc = nullptr, evB = nullptr,
                       evJoin = nullptr;
    if (s2 == nullptr) {
        cudaStreamCreateWithFlags(&s2, cudaStreamNonBlocking);
        cudaEventCreateWithFlags(&evFork, cudaEventDisableTiming);
        cudaEventCreateWithFlags(&evSc, cudaEventDisableTiming);
        cudaEventCreateWithFlags(&evB, cudaEventDisableTiming);
        cudaEventCreateWithFlags(&evJoin, cudaEventDisableTiming);
    }

    int nrt = (n_nodes + 127) / 128;
    int n8 = n_nodes * DIM_H / 8;
    int nbN = (n8 + 255) / 256;
    int nbW = 32;

    // Fork side stream at graph start
    cudaEventRecord(evFork, 0);
    cudaStreamWaitEvent(s2, evFork, 0);

    // Main: scatter starts immediately (reads fp32 nodes; S/deg zero at entry)
    scatter_kernel<<<((n_edges + 1) / 2 * 32 + 255) / 256, 256>>>(
        esrc, edst, nodes, n_edges);
    cudaEventRecord(evSc, 0);

    // Side: wprod -> prep (nh/colsum/weights) -> bias2bm, all under scatter
    wprod_kernel<<<DIM_3H, DIM_H, 0, s2>>>(w_ih, W_msg);
    prep_kernel<<<nbN + nbW, 256, 0, s2>>>(nodes, W_msg, w_hh, n8, nbN);
    bias2bm_kernel<<<12, 1024, 0, s2>>>(w_ih, b_ih, b_msg, n_nodes);
    cudaEventRecord(evB, s2);

    // Side: gemmGH after scatter (concurrent with gemmMG, both tensor-bound)
    cudaStreamWaitEvent(s2, evSc, 0);
    gemm_ws<<<dim3(3, 74), 512, SM_TOTAL, s2>>>(
        pNh, pWhh, b_hh, b_hh + 128, nullptr, nullptr, nullptr,
        pGhh, DIM_3H, pGhh + 128, DIM_3H, n_nodes, nrt, 74);
    cudaEventRecord(evJoin, s2);

    // Main: [messages | gi] = S @ [W_msg; Wc2]^T + deg*bvec + bias
    cudaStreamWaitEvent(0, evB, 0);
    gemm_ws<<<dim3(4, 37), 512, SM_TOTAL>>>(
        pS, pWc, nullptr, pBias2, b_msg, pBm2, pDeg,
        pMsg, DIM_H, pGih, DIM_3H, n_nodes, nrt, 37);

    // Join: gru_ln needs gh from s2
    cudaStreamWaitEvent(0, evJoin, 0);
    gru_ln_kernel<<<(n_nodes + 7) / 8, 256>>>(nodes, gamma, beta, out, n_nodes);
}

// round 15
// speedup vs baseline: 1.5549x; 1.1362x over previous
#include <cuda_runtime.h>
#include <cuda_fp16.h>
#include <math.h>
#include <stdint.h>

#define DIM_H  128
#define DIM_3H 384
#define MAX_N  50000
#define MAX_E  600000
#define LN_EPS 1e-5f

// ---------------------------------------------------------------------------
// Scratch (device globals: allocation-free per harness rules)
// g_colsum contract: zero at entry (zero-init on load; re-zeroed by gru_ln).
// g_msg zeroed by prep each run.
// ---------------------------------------------------------------------------
__device__ __align__(256) __half g_msg[MAX_N * DIM_H];   // messages (fp16)
__device__ float  g_colsum[DIM_H];

__device__ __align__(256) __half g_Th[MAX_N * DIM_H];    // T (fp16)
__device__ __align__(256) __half g_ghh[MAX_N * DIM_3H];  // gh (fp16)
__device__ __align__(256) __half g_gih[MAX_N * DIM_3H];  // gi (fp16)

__device__ __align__(256) __half g_nh[MAX_N * DIM_H];    // nodes fp16
__device__ __align__(256) __half g_Wcat[512 * DIM_H];    // [W_msg; w_hh] fp16
__device__ __align__(256) __half g_Wih[DIM_3H * DIM_H];  // w_ih fp16

// ---------------------------------------------------------------------------
// PTX helpers (arch-neutral sm_80+/sm_90)
// ---------------------------------------------------------------------------
__device__ __forceinline__ uint32_t smem_u32(const void* p) {
    uint32_t a;
    asm("{ .reg .u64 t; cvta.to.shared.u64 t, %1; cvt.u32.u64 %0, t; }"
        : "=r"(a) : "l"(p));
    return a;
}

__device__ __forceinline__ void ldsm_x4(uint32_t& r0, uint32_t& r1,
                                        uint32_t& r2, uint32_t& r3,
                                        uint32_t addr) {
    asm volatile("ldmatrix.sync.aligned.m8n8.x4.shared.b16 {%0,%1,%2,%3}, [%4];"
                 : "=r"(r0), "=r"(r1), "=r"(r2), "=r"(r3) : "r"(addr));
}

__device__ __forceinline__ void mma_f16(float* d, uint32_t a0, uint32_t a1,
                                        uint32_t a2, uint32_t a3,
                                        uint32_t b0, uint32_t b1) {
    asm volatile(
        "mma.sync.aligned.m16n8k16.row.col.f32.f16.f16.f32 "
        "{%0,%1,%2,%3}, {%4,%5,%6,%7}, {%8,%9}, {%0,%1,%2,%3};"
        : "+f"(d[0]), "+f"(d[1]), "+f"(d[2]), "+f"(d[3])
        : "r"(a0), "r"(a1), "r"(a2), "r"(a3), "r"(b0), "r"(b1));
}

#define CP_ASYNC16(dst, src, sz)                                               \
    asm volatile("cp.async.cg.shared.global [%0], [%1], 16, %2;"               \
                 :: "r"(dst), "l"(src), "r"(sz) : "memory")
#define CP_COMMIT() asm volatile("cp.async.commit_group;" ::: "memory")
#define CP_WAIT0()  asm volatile("cp.async.wait_group 0;" ::: "memory")
#define CP_WAIT1()  asm volatile("cp.async.wait_group 1;" ::: "memory")

// 4 halfs -> 4 floats
__device__ __forceinline__ void ld4h(const __half* p, float* o) {
    uint2 u = *reinterpret_cast<const uint2*>(p);
    __half2 a = *reinterpret_cast<__half2*>(&u.x);
    __half2 b = *reinterpret_cast<__half2*>(&u.y);
    float2 fa = __half22float2(a), fb = __half22float2(b);
    o[0] = fa.x; o[1] = fa.y; o[2] = fb.x; o[3] = fb.y;
}

// ---------------------------------------------------------------------------
// Fused prep kernel. Blocks [0, nbN): nodes fp32->fp16 + colsum atomics +
// zero g_msg. Blocks [nbN, nbN+56): W_msg/w_hh -> Wcat, w_ih -> Wih.
// ---------------------------------------------------------------------------
__global__ void prep_kernel(const float* __restrict__ nodes,
                            const float* __restrict__ W_msg,
                            const float* __restrict__ w_hh,
                            const float* __restrict__ w_ih,
                            int n8, int nbN) {
    int tid = threadIdx.x;
    if ((int)blockIdx.x >= nbN) {
        int i = (blockIdx.x - nbN) * 256 + tid;
        const float* src;
        __half* dst;
        int j;
        if (i < 2048)       { src = W_msg; dst = g_Wcat;          j = i; }
        else if (i < 8192)  { src = w_hh;  dst = g_Wcat + 16384;  j = i - 2048; }
        else if (i < 14336) { src = w_ih;  dst = g_Wih;           j = i - 8192; }
        else return;
        float4 v0 = reinterpret_cast<const float4*>(src)[j * 2];
        float4 v1 = reinterpret_cast<const float4*>(src)[j * 2 + 1];
        float xs[8] = {v0.x, v0.y, v0.z, v0.w, v1.x, v1.y, v1.z, v1.w};
        uint32_t hb[8];
#pragma unroll
        for (int t = 0; t < 8; t++)
            hb[t] = (uint32_t)__half_as_ushort(__float2half_rn(xs[t]));
        reinterpret_cast<uint4*>(dst)[j] =
            make_uint4(hb[0] | (hb[1] << 16), hb[2] | (hb[3] << 16),
                       hb[4] | (hb[5] << 16), hb[6] | (hb[7] << 16));
        return;
    }
    // nodes part
    __shared__ float cs[DIM_H];
    if (tid < DIM_H) cs[tid] = 0.f;
    __syncthreads();
    int i = blockIdx.x * 256 + tid;
    int lane = tid & 31;
    float xs[8] = {0.f, 0.f, 0.f, 0.f, 0.f, 0.f, 0.f, 0.f};
    if (i < n8) {
        reinterpret_cast<uint4*>(g_msg)[i] = make_uint4(0, 0, 0, 0);
        float4 v0 = reinterpret_cast<const float4*>(nodes)[i * 2];
        float4 v1 = reinterpret_cast<const float4*>(nodes)[i * 2 + 1];
        xs[0] = v0.x; xs[1] = v0.y; xs[2] = v0.z; xs[3] = v0.w;
        xs[4] = v1.x; xs[5] = v1.y; xs[6] = v1.z; xs[7] = v1.w;
        uint32_t hb[8];
#pragma unroll
        for (int t = 0; t < 8; t++)
            hb[t] = (uint32_t)__half_as_ushort(__float2half_rn(xs[t]));
        reinterpret_cast<uint4*>(g_nh)[i] =
            make_uint4(hb[0] | (hb[1] << 16), hb[2] | (hb[3] << 16),
                       hb[4] | (hb[5] << 16), hb[6] | (hb[7] << 16));
    }
#pragma unroll
    for (int t = 0; t < 8; t++)
        xs[t] += __shfl_down_sync(0xFFFFFFFF, xs[t], 16);
    if (lane < 16) {
        int c0 = lane * 8;
#pragma unroll
        for (int t = 0; t < 8; t++) atomicAdd(&cs[c0 + t], xs[t]);
    }
    __syncthreads();
    if (tid < DIM_H) atomicAdd(&g_colsum[tid], cs[tid]);
}

// ---------------------------------------------------------------------------
// Weight-stationary tensor-core GEMM (single fp16 product, fp32 accum).
// Optional bias fold: if w_fold != null, per-CTA prologue adds
// dot(w_fold[global_col], colsum*inv_n) to the column bias — replaces the
// separate bias2 kernel with bit-identical arithmetic.
// ---------------------------------------------------------------------------
#define LDA 136
#define TILE_B (128 * LDA * 2)        // 34816 B per fp16 tile
#define SM_B    0
#define SM_A0   TILE_B
#define SM_A1   (2 * TILE_B)
#define SM_BIAS (3 * TILE_B)          // [0:128) bias, [128:256) mean
#define SM_TOTAL (SM_BIAS + 1024)

__device__ __forceinline__ void cp_tile(uint32_t sdst, const __half* gsrc,
                                        int rows_valid) {
    int tid = threadIdx.x;
#pragma unroll
    for (int i = 0; i < 4; i++) {
        int idx = tid + i * 512;          // 2048 chunks of 16B
        int r = idx >> 4, c = idx & 15;
        uint32_t d = sdst + (uint32_t)(r * LDA + c * 8) * 2;
        int ok = (r < rows_valid);
        const __half* s = gsrc + (size_t)(ok ? r : 0) * DIM_H + c * 8;
        CP_ASYNC16(d, s, ok ? 16 : 0);
    }
}

__global__ void __launch_bounds__(512, 1)
gemm_ws(const __half* __restrict__ A,
        const __half* __restrict__ B,
        const float* __restrict__ bias0,
        const float* __restrict__ bias1,
        const float* __restrict__ w_fold,
        const float* __restrict__ colsum,
        float inv_n,
        __half* __restrict__ C0, int ldc0,
        __half* __restrict__ C1, int ldc1,
        int n_rows, int nrt, int nslices) {
    extern __shared__ char sm[];
    uint32_t smb = smem_u32(sm);
    const int tid = threadIdx.x;
    const int wid = tid >> 5;
    const int lane = tid & 31;
    const int ct = blockIdx.x;
    const int slice = blockIdx.y;

    const uint32_t bufA[2] = {SM_A0, SM_A1};

    cp_tile(smb + SM_B, B + (size_t)ct * 128 * DIM_H, 128);
    cp_tile(smb + bufA[0], A + (size_t)slice * 128 * DIM_H,
            n_rows - slice * 128);
    CP_COMMIT();

    float* bias_s = reinterpret_cast<float*>(sm + SM_BIAS);
    if (tid < 128) {
        const float* bp = (ct == 0) ? bias0 : bias1;
        int off = (ct == 0) ? tid : (ct - 1) * 128 + tid;
        bias_s[tid] = bp ? bp[off] : 0.f;
        if (w_fold) bias_s[128 + tid] = colsum[tid] * inv_n;
    }
    if (w_fold) {
        __syncthreads();
        // 16 warps x 8 rows each: bias_s[rr] += dot(w_fold[gcol], mean)
#pragma unroll
        for (int q = 0; q < 8; q++) {
            int rr = wid * 8 + q;
            int gcol = ct * 128 + rr;
            float acc = 0.f;
#pragma unroll
            for (int j = 0; j < 4; j++) {
                int k = lane + j * 32;
                acc = fmaf(w_fold[(size_t)gcol * DIM_H + k], bias_s[128 + k],
                           acc);
            }
#pragma unroll
            for (int off = 16; off > 0; off >>= 1)
                acc += __shfl_xor_sync(0xFFFFFFFF, acc, off);
            if (lane == 0) bias_s[rr] += acc;
        }
    }

    const int wr = wid & 7;
    const int wc = wid >> 3;

    const int a_m = lane & 15;
    const int a_k = (lane >> 4) * 8;
    const uint32_t offA = (uint32_t)(((wr * 16 + a_m) * LDA + a_k) * 2);

    const int b_n = (lane & 7) + (lane >> 4) * 8;
    const int b_k = ((lane >> 3) & 1) * 8;
    uint32_t offB[4];
#pragma unroll
    for (int p = 0; p < 4; p++)
        offB[p] = (uint32_t)(((wc * 64 + p * 16 + b_n) * LDA + b_k) * 2);

    const int r_in = lane >> 2;
    const int c_in = (lane & 3) * 2;

    __half* Cp;
    int ldc, colbase;
    if (ct == 0) { Cp = C0; ldc = ldc0; colbase = 0; }
    else         { Cp = C1; ldc = ldc1; colbase = (ct - 1) * 128; }

    int nbuf = 0;
    for (int it = slice; it < nrt; it += nslices) {
        int next = it + nslices;
        __syncthreads();
        if (next < nrt) {
            cp_tile(smb + bufA[nbuf ^ 1], A + (size_t)next * 128 * DIM_H,
                    n_rows - next * 128);
            CP_COMMIT();
            CP_WAIT1();
        } else {
            CP_WAIT0();
        }
        __syncthreads();

        const uint32_t a_b = smb + bufA[nbuf];

        float acc[8][4];
#pragma unroll
        for (int nt = 0; nt < 8; nt++)
#pragma unroll
            for (int e = 0; e < 4; e++) acc[nt][e] = 0.f;

#pragma unroll
        for (int ks = 0; ks < 8; ks++) {
            const uint32_t kb = ks * 32;
            uint32_t a0, a1, a2, a3;
            ldsm_x4(a0, a1, a2, a3, a_b + offA + kb);
#pragma unroll
            for (int p = 0; p < 4; p++) {
                uint32_t b0, b1, b2, b3;
                ldsm_x4(b0, b1, b2, b3, smb + SM_B + offB[p] + kb);
                mma_f16(acc[2 * p],     a0, a1, a2, a3, b0, b1);
                mma_f16(acc[2 * p + 1], a0, a1, a2, a3, b2, b3);
            }
        }

        const int row_a = it * 128 + wr * 16 + r_in;
        const int row_b = row_a + 8;
#pragma unroll
        for (int nt = 0; nt < 8; nt++) {
            int cb = wc * 64 + nt * 8 + c_in;
            int cl = colbase + cb;
            float bx = bias_s[cb], by = bias_s[cb + 1];
            if (row_a < n_rows)
                *reinterpret_cast<__half2*>(Cp + (size_t)row_a * ldc + cl) =
                    __floats2half2_rn(acc[nt][0] + bx, acc[nt][1] + by);
            if (row_b < n_rows)
                *reinterpret_cast<__half2*>(Cp + (size_t)row_b * ldc + cl) =
                    __floats2half2_rn(acc[nt][2] + bx, acc[nt][3] + by);
        }
        nbuf ^= 1;
    }
}

// ---------------------------------------------------------------------------
// Edge scatter: TWO edges per warp (16 lanes each, 16B per lane).
// messages[dst] += fp16(T[src] + b_msg) via red.global.add.noftz.v4.f16x2
// ---------------------------------------------------------------------------
__global__ void scatter_kernel(const int* __restrict__ esrc,
                               const int* __restrict__ edst,
                               const float* __restrict__ b_msg, int n_edges) {
    int gwarp = (blockIdx.x * blockDim.x + threadIdx.x) >> 5;
    int lane  = threadIdx.x & 31;
    int e = gwarp * 2 + (lane >> 4);
    int hl = lane & 15;
    if (e >= n_edges) return;
    int s = esrc[e];
    int d = edst[e];
    uint4 tv = *reinterpret_cast<const uint4*>(g_Th + (size_t)s * DIM_H + hl * 8);
    float4 b0 = *reinterpret_cast<const float4*>(b_msg + hl * 8);
    float4 b1 = *reinterpret_cast<const float4*>(b_msg + hl * 8 + 4);
    float bb[8] = {b0.x, b0.y, b0.z, b0.w, b1.x, b1.y, b1.z, b1.w};
    uint32_t tw[4] = {tv.x, tv.y, tv.z, tv.w};
    uint32_t r[4];
#pragma unroll
    for (int j = 0; j < 4; j++) {
        __half2 h = *reinterpret_cast<__half2*>(&tw[j]);
        float2 f = __half22float2(h);
        __half2 o = __floats2half2_rn(f.x + bb[2 * j], f.y + bb[2 * j + 1]);
        r[j] = *reinterpret_cast<uint32_t*>(&o);
    }
    __half* p = g_msg + (size_t)d * DIM_H + hl * 8;
    asm volatile("red.global.add.noftz.v4.f16x2 [%0], {%1, %2, %3, %4};"
                 :: "l"(p), "r"(r[0]), "r"(r[1]), "r"(r[2]), "r"(r[3])
                 : "memory");
}

// ---------------------------------------------------------------------------
// Fused GRU gates + LayerNorm + message residual. One warp per node.
// Re-zeroes g_colsum for the next graph replay (block 0).
// ---------------------------------------------------------------------------
__device__ __forceinline__ float sigmoidf_(float x) {
    return 1.0f / (1.0f + expf(-x));
}

__global__ void gru_ln_kernel(const float* __restrict__ nodes,
                              const float* __restrict__ gamma,
                              const float* __restrict__ beta,
                              float* __restrict__ out, int n_nodes) {
    if (blockIdx.x == 0 && threadIdx.x < DIM_H)
        g_colsum[threadIdx.x] = 0.f;

    int gwarp = (blockIdx.x * blockDim.x + threadIdx.x) >> 5;
    int lane  = threadIdx.x & 31;
    if (gwarp >= n_nodes) return;

    size_t base = (size_t)gwarp * DIM_H;
    size_t gb   = (size_t)gwarp * DIM_3H;
    int le = lane * 4;

    float4 h4 = reinterpret_cast<const float4*>(nodes + base)[lane];

    float mm[4], ir[4], iz[4], in_[4], hr[4], hz[4], hn[4];
    ld4h(g_msg + base + le, mm);
    ld4h(g_gih + gb + le, ir);
    ld4h(g_gih + gb + 128 + le, iz);
    ld4h(g_gih + gb + 256 + le, in_);
    ld4h(g_ghh + gb + le, hr);
    ld4h(g_ghh + gb + 128 + le, hz);
    ld4h(g_ghh + gb + 256 + le, hn);

    float hh[4] = {h4.x, h4.y, h4.z, h4.w};

    float hx[4];
    float s = 0.f, s2 = 0.f;
#pragma unroll
    for (int c = 0; c < 4; c++) {
        float r = sigmoidf_(ir[c] + hr[c]);
        float z = sigmoidf_(iz[c] + hz[c]);
        float n = tanhf(in_[c] + r * hn[c]);
        hx[c] = (1.0f - z) * n + z * hh[c];
        s  += hx[c];
        s2 += hx[c] * hx[c];
    }
#pragma unroll
    for (int off = 16; off > 0; off >>= 1) {
        s  += __shfl_xor_sync(0xFFFFFFFF, s,  off);
        s2 += __shfl_xor_sync(0xFFFFFFFF, s2, off);
    }
    float mu   = s  * (1.0f / DIM_H);
    float var  = s2 * (1.0f / DIM_H) - mu * mu;
    float rstd = rsqrtf(var + LN_EPS);

    float4 g4 = reinterpret_cast<const float4*>(gamma)[lane];
    float4 b4 = reinterpret_cast<const float4*>(beta)[lane];
    float gg[4] = {g4.x, g4.y, g4.z, g4.w};
    float bb[4] = {b4.x, b4.y, b4.z, b4.w};

    float o[4];
#pragma unroll
    for (int c = 0; c < 4; c++)
        o[c] = gg[c] * (hx[c] - mu) * rstd + bb[c] + mm[c];

    reinterpret_cast<float4*>(out + base)[lane] =
        make_float4(o[0], o[1], o[2], o[3]);
}

// ---------------------------------------------------------------------------
// Launch. Graph (round-11 structure, bias2 folded into gemm2):
//   main: prep (evFork) -> gemmT -> scatter -> gemm2(+bias fold)
//         -> [wait evJoin] gru_ln
//   s2:   [wait evFork] gemmGH (evJoin)
// ---------------------------------------------------------------------------
extern "C" void kernel_launch(void* const* d_in, const int* in_sizes, int n_in,
                              void* d_out, int out_size) {
    const float* nodes = (const float*)d_in[0];
    const float* W_msg = (const float*)d_in[1];
    const float* b_msg = (const float*)d_in[2];
    const float* w_ih  = (const float*)d_in[3];
    const float* w_hh  = (const float*)d_in[4];
    const float* b_ih  = (const float*)d_in[5];
    const float* b_hh  = (const float*)d_in[6];
    const float* gamma = (const float*)d_in[7];
    const float* beta  = (const float*)d_in[8];
    const int*   esrc  = (const int*)d_in[9];
    const int*   edst  = (const int*)d_in[10];
    float* out = (float*)d_out;

    int n_nodes = in_sizes[0] / DIM_H;
    int n_edges = in_sizes[9];

    float *pColsum;
    __half *pMsg, *pTh, *pGhh, *pGih, *pNh, *pWc, *pWi;
    cudaGetSymbolAddress((void**)&pColsum, g_colsum);
    cudaGetSymbolAddress((void**)&pMsg, g_msg);
    cudaGetSymbolAddress((void**)&pTh,  g_Th);
    cudaGetSymbolAddress((void**)&pGhh, g_ghh);
    cudaGetSymbolAddress((void**)&pGih, g_gih);
    cudaGetSymbolAddress((void**)&pNh,  g_nh);
    cudaGetSymbolAddress((void**)&pWc,  g_Wcat);
    cudaGetSymbolAddress((void**)&pWi,  g_Wih);

    cudaFuncSetAttribute(gemm_ws,
                         cudaFuncAttributeMaxDynamicSharedMemorySize, SM_TOTAL);

    static cudaStream_t s2 = nullptr;
    static cudaEvent_t evFork = nullptr, evJoin = nullptr;
    if (s2 == nullptr) {
        cudaStreamCreateWithFlags(&s2, cudaStreamNonBlocking);
        cudaEventCreateWithFlags(&evFork, cudaEventDisableTiming);
        cudaEventCreateWithFlags(&evJoin, cudaEventDisableTiming);
    }

    int nrt = (n_nodes + 127) / 128;
    int n8 = n_nodes * DIM_H / 8;
    int nbN = (n8 + 255) / 256;
    int nbW = 56;  // 14336 / 256

    // 1: fused prep (nodes convert + colsum + msg zero; all weight converts)
    prep_kernel<<<nbN + nbW, 256>>>(nodes, W_msg, w_hh, w_ih, n8, nbN);

    // Fork: gh = nodes @ w_hh^T + b_hh on s2 (overlaps gemmT + scatter)
    cudaEventRecord(evFork, 0);
    cudaStreamWaitEvent(s2, evFork, 0);
    gemm_ws<<<dim3(3, 49), 512, SM_TOTAL, s2>>>(
        pNh, pWc + 128 * DIM_H, b_hh, b_hh + 128, nullptr, nullptr, 0.f,
        pGhh, DIM_3H, pGhh + 128, DIM_3H, n_nodes, nrt, 49);
    cudaEventRecord(evJoin, s2);

    // 2: T = nodes @ W_msg^T (one wave)
    gemm_ws<<<dim3(1, 148), 512, SM_TOTAL>>>(
        pNh, pWc, nullptr, nullptr, nullptr, nullptr, 0.f,
        pTh, DIM_H, pTh, DIM_H, n_nodes, nrt, 148);

    // 3: messages[dst] += T[src] + b_msg   (v4.f16x2 reductions)
    scatter_kernel<<<((n_edges + 1) / 2 * 32 + 255) / 256, 256>>>(
        esrc, edst, b_msg, n_edges);

    // 4: gi = msg @ w_ih^T + b_ih + w_ih@mean   (bias2 folded in prologue)
    gemm_ws<<<dim3(3, 49), 512, SM_TOTAL>>>(
        pMsg, pWi, b_ih, b_ih + 128, w_ih, pColsum, 1.0f / (float)n_nodes,
        pGih, DIM_3H, pGih + 128, DIM_3H, n_nodes, nrt, 49);

    // 5: gru_ln needs gh from s2
    cudaStreamWaitEvent(0, evJoin, 0);
    gru_ln_kernel<<<(n_nodes + 7) / 8, 256>>>(nodes, gamma, beta, out, n_nodes);
}

// round 16
// speedup vs baseline: 1.6911x; 1.0876x over previous
#include <cuda_runtime.h>
#include <cuda_fp16.h>
#include <math.h>
#include <stdint.h>

#define DIM_H  128
#define DIM_3H 384
#define MAX_N  50000
#define MAX_E  600000
#define LN_EPS 1e-5f

// ---------------------------------------------------------------------------
// Scratch (device globals: allocation-free per harness rules)
// g_colsum contract: zero at entry (zero-init on load; re-zeroed by gru_ln).
// g_msg zeroed by prep each run.
// ---------------------------------------------------------------------------
__device__ __align__(256) __half g_msg[MAX_N * DIM_H];   // messages (fp16)
__device__ float  g_colsum[DIM_H];
__device__ float  g_bias2[DIM_3H];            // b_ih + w_ih @ mean(nodes)

__device__ __align__(256) __half g_Th[MAX_N * DIM_H];    // T (fp16)
__device__ __align__(256) __half g_ghh[MAX_N * DIM_3H];  // gh (fp16)
__device__ __align__(256) __half g_gih[MAX_N * DIM_3H];  // gi (fp16)

__device__ __align__(256) __half g_nh[MAX_N * DIM_H];    // nodes fp16
__device__ __align__(256) __half g_Wcat[512 * DIM_H];    // [W_msg; w_hh] fp16
__device__ __align__(256) __half g_Wih[DIM_3H * DIM_H];  // w_ih fp16

// ---------------------------------------------------------------------------
// PTX helpers (arch-neutral sm_80+/sm_90)
// ---------------------------------------------------------------------------
__device__ __forceinline__ uint32_t smem_u32(const void* p) {
    uint32_t a;
    asm("{ .reg .u64 t; cvta.to.shared.u64 t, %1; cvt.u32.u64 %0, t; }"
        : "=r"(a) : "l"(p));
    return a;
}

__device__ __forceinline__ void ldsm_x4(uint32_t& r0, uint32_t& r1,
                                        uint32_t& r2, uint32_t& r3,
                                        uint32_t addr) {
    asm volatile("ldmatrix.sync.aligned.m8n8.x4.shared.b16 {%0,%1,%2,%3}, [%4];"
                 : "=r"(r0), "=r"(r1), "=r"(r2), "=r"(r3) : "r"(addr));
}

__device__ __forceinline__ void mma_f16(float* d, uint32_t a0, uint32_t a1,
                                        uint32_t a2, uint32_t a3,
                                        uint32_t b0, uint32_t b1) {
    asm volatile(
        "mma.sync.aligned.m16n8k16.row.col.f32.f16.f16.f32 "
        "{%0,%1,%2,%3}, {%4,%5,%6,%7}, {%8,%9}, {%0,%1,%2,%3};"
        : "+f"(d[0]), "+f"(d[1]), "+f"(d[2]), "+f"(d[3])
        : "r"(a0), "r"(a1), "r"(a2), "r"(a3), "r"(b0), "r"(b1));
}

#define CP_ASYNC16(dst, src, sz)                                               \
    asm volatile("cp.async.cg.shared.global [%0], [%1], 16, %2;"               \
                 :: "r"(dst), "l"(src), "r"(sz) : "memory")
#define CP_COMMIT() asm volatile("cp.async.commit_group;" ::: "memory")
#define CP_WAIT0()  asm volatile("cp.async.wait_group 0;" ::: "memory")
#define CP_WAIT1()  asm volatile("cp.async.wait_group 1;" ::: "memory")

// 4 halfs -> 4 floats
__device__ __forceinline__ void ld4h(const __half* p, float* o) {
    uint2 u = *reinterpret_cast<const uint2*>(p);
    __half2 a = *reinterpret_cast<__half2*>(&u.x);
    __half2 b = *reinterpret_cast<__half2*>(&u.y);
    float2 fa = __half22float2(a), fb = __half22float2(b);
    o[0] = fa.x; o[1] = fa.y; o[2] = fb.x; o[3] = fb.y;
}

// ---------------------------------------------------------------------------
// Fused prep kernel. Blocks [0, nbN): nodes fp32->fp16 + colsum atomics +
// zero g_msg. Blocks [nbN, nbN+56): W_msg/w_hh -> Wcat, w_ih -> Wih.
// ---------------------------------------------------------------------------
__global__ void prep_kernel(const float* __restrict__ nodes,
                            const float* __restrict__ W_msg,
                            const float* __restrict__ w_hh,
                            const float* __restrict__ w_ih,
                            int n8, int nbN) {
    int tid = threadIdx.x;
    if ((int)blockIdx.x >= nbN) {
        int i = (blockIdx.x - nbN) * 256 + tid;
        const float* src;
        __half* dst;
        int j;
        if (i < 2048)       { src = W_msg; dst = g_Wcat;          j = i; }
        else if (i < 8192)  { src = w_hh;  dst = g_Wcat + 16384;  j = i - 2048; }
        else if (i < 14336) { src = w_ih;  dst = g_Wih;           j = i - 8192; }
        else return;
        float4 v0 = reinterpret_cast<const float4*>(src)[j * 2];
        float4 v1 = reinterpret_cast<const float4*>(src)[j * 2 + 1];
        float xs[8] = {v0.x, v0.y, v0.z, v0.w, v1.x, v1.y, v1.z, v1.w};
        uint32_t hb[8];
#pragma unroll
        for (int t = 0; t < 8; t++)
            hb[t] = (uint32_t)__half_as_ushort(__float2half_rn(xs[t]));
        reinterpret_cast<uint4*>(dst)[j] =
            make_uint4(hb[0] | (hb[1] << 16), hb[2] | (hb[3] << 16),
                       hb[4] | (hb[5] << 16), hb[6] | (hb[7] << 16));
        return;
    }
    // nodes part
    __shared__ float cs[DIM_H];
    if (tid < DIM_H) cs[tid] = 0.f;
    __syncthreads();
    int i = blockIdx.x * 256 + tid;
    int lane = tid & 31;
    float xs[8] = {0.f, 0.f, 0.f, 0.f, 0.f, 0.f, 0.f, 0.f};
    if (i < n8) {
        reinterpret_cast<uint4*>(g_msg)[i] = make_uint4(0, 0, 0, 0);
        float4 v0 = reinterpret_cast<const float4*>(nodes)[i * 2];
        float4 v1 = reinterpret_cast<const float4*>(nodes)[i * 2 + 1];
        xs[0] = v0.x; xs[1] = v0.y; xs[2] = v0.z; xs[3] = v0.w;
        xs[4] = v1.x; xs[5] = v1.y; xs[6] = v1.z; xs[7] = v1.w;
        uint32_t hb[8];
#pragma unroll
        for (int t = 0; t < 8; t++)
            hb[t] = (uint32_t)__half_as_ushort(__float2half_rn(xs[t]));
        reinterpret_cast<uint4*>(g_nh)[i] =
            make_uint4(hb[0] | (hb[1] << 16), hb[2] | (hb[3] << 16),
                       hb[4] | (hb[5] << 16), hb[6] | (hb[7] << 16));
    }
#pragma unroll
    for (int t = 0; t < 8; t++)
        xs[t] += __shfl_down_sync(0xFFFFFFFF, xs[t], 16);
    if (lane < 16) {
        int c0 = lane * 8;
#pragma unroll
        for (int t = 0; t < 8; t++) atomicAdd(&cs[c0 + t], xs[t]);
    }
    __syncthreads();
    if (tid < DIM_H) atomicAdd(&g_colsum[tid], cs[tid]);
}

// bias2 = b_ih + w_ih @ (colsum / n): one warp per row. launch <<<12, 1024>>>
__global__ void bias2_fast(const float* __restrict__ w_ih,
                           const float* __restrict__ b_ih, int n_nodes) {
    __shared__ float mean_s[DIM_H];
    int tid = threadIdx.x;
    if (tid < DIM_H) mean_s[tid] = g_colsum[tid] * (1.0f / (float)n_nodes);
    __syncthreads();
    int r = (blockIdx.x * blockDim.x + tid) >> 5;  // 0..383
    int lane = tid & 31;
    if (r >= DIM_3H) return;
    float acc = 0.f;
#pragma unroll
    for (int j = 0; j < 4; j++) {
        int k = lane + j * 32;
        acc = fmaf(w_ih[(size_t)r * DIM_H + k], mean_s[k], acc);
    }
#pragma unroll
    for (int off = 16; off > 0; off >>= 1)
        acc += __shfl_xor_sync(0xFFFFFFFF, acc, off);
    if (lane == 0) g_bias2[r] = acc + b_ih[r];
}

// ---------------------------------------------------------------------------
// Weight-stationary tensor-core GEMM (single fp16 product, fp32 accum).
// ---------------------------------------------------------------------------
#define LDA 136
#define TILE_B (128 * LDA * 2)        // 34816 B per fp16 tile
#define SM_B    0
#define SM_A0   TILE_B
#define SM_A1   (2 * TILE_B)
#define SM_BIAS (3 * TILE_B)
#define SM_TOTAL (SM_BIAS + 512)

__device__ __forceinline__ void cp_tile(uint32_t sdst, const __half* gsrc,
                                        int rows_valid) {
    int tid = threadIdx.x;
#pragma unroll
    for (int i = 0; i < 4; i++) {
        int idx = tid + i * 512;          // 2048 chunks of 16B
        int r = idx >> 4, c = idx & 15;
        uint32_t d = sdst + (uint32_t)(r * LDA + c * 8) * 2;
        int ok = (r < rows_valid);
        const __half* s = gsrc + (size_t)(ok ? r : 0) * DIM_H + c * 8;
        CP_ASYNC16(d, s, ok ? 16 : 0);
    }
}

__global__ void __launch_bounds__(512, 1)
gemm_ws(const __half* __restrict__ A,
        const __half* __restrict__ B,
        const float* __restrict__ bias0,
        const float* __restrict__ bias1,
        __half* __restrict__ C0, int ldc0,
        __half* __restrict__ C1, int ldc1,
        int n_rows, int nrt, int nslices) {
    extern __shared__ char sm[];
    uint32_t smb = smem_u32(sm);
    const int tid = threadIdx.x;
    const int wid = tid >> 5;
    const int lane = tid & 31;
    const int ct = blockIdx.x;
    const int slice = blockIdx.y;

    const uint32_t bufA[2] = {SM_A0, SM_A1};

    cp_tile(smb + SM_B, B + (size_t)ct * 128 * DIM_H, 128);
    cp_tile(smb + bufA[0], A + (size_t)slice * 128 * DIM_H,
            n_rows - slice * 128);
    CP_COMMIT();

    float* bias_s = reinterpret_cast<float*>(sm + SM_BIAS);
    if (tid < 128)
        bias_s[tid] = (ct == 0) ? (bias0 ? bias0[tid] : 0.f)
                                : (bias1 ? bias1[(ct - 1) * 128 + tid] : 0.f);

    const int wr = wid & 7;
    const int wc = wid >> 3;

    const int a_m = lane & 15;
    const int a_k = (lane >> 4) * 8;
    const uint32_t offA = (uint32_t)(((wr * 16 + a_m) * LDA + a_k) * 2);

    const int b_n = (lane & 7) + (lane >> 4) * 8;
    const int b_k = ((lane >> 3) & 1) * 8;
    uint32_t offB[4];
#pragma unroll
    for (int p = 0; p < 4; p++)
        offB[p] = (uint32_t)(((wc * 64 + p * 16 + b_n) * LDA + b_k) * 2);

    const int r_in = lane >> 2;
    const int c_in = (lane & 3) * 2;

    __half* Cp;
    int ldc, colbase;
    if (ct == 0) { Cp = C0; ldc = ldc0; colbase = 0; }
    else         { Cp = C1; ldc = ldc1; colbase = (ct - 1) * 128; }

    int nbuf = 0;
    for (int it = slice; it < nrt; it += nslices) {
        int next = it + nslices;
        __syncthreads();
        if (next < nrt) {
            cp_tile(smb + bufA[nbuf ^ 1], A + (size_t)next * 128 * DIM_H,
                    n_rows - next * 128);
            CP_COMMIT();
            CP_WAIT1();
        } else {
            CP_WAIT0();
        }
        __syncthreads();

        const uint32_t a_b = smb + bufA[nbuf];

        float acc[8][4];
#pragma unroll
        for (int nt = 0; nt < 8; nt++)
#pragma unroll
            for (int e = 0; e < 4; e++) acc[nt][e] = 0.f;

#pragma unroll
        for (int ks = 0; ks < 8; ks++) {
            const uint32_t kb = ks * 32;
            uint32_t a0, a1, a2, a3;
            ldsm_x4(a0, a1, a2, a3, a_b + offA + kb);
#pragma unroll
            for (int p = 0; p < 4; p++) {
                uint32_t b0, b1, b2, b3;
                ldsm_x4(b0, b1, b2, b3, smb + SM_B + offB[p] + kb);
                mma_f16(acc[2 * p],     a0, a1, a2, a3, b0, b1);
                mma_f16(acc[2 * p + 1], a0, a1, a2, a3, b2, b3);
            }
        }

        const int row_a = it * 128 + wr * 16 + r_in;
        const int row_b = row_a + 8;
#pragma unroll
        for (int nt = 0; nt < 8; nt++) {
            int cb = wc * 64 + nt * 8 + c_in;
            int cl = colbase + cb;
            float bx = bias_s[cb], by = bias_s[cb + 1];
            if (row_a < n_rows)
                *reinterpret_cast<__half2*>(Cp + (size_t)row_a * ldc + cl) =
                    __floats2half2_rn(acc[nt][0] + bx, acc[nt][1] + by);
            if (row_b < n_rows)
                *reinterpret_cast<__half2*>(Cp + (size_t)row_b * ldc + cl) =
                    __floats2half2_rn(acc[nt][2] + bx, acc[nt][3] + by);
        }
        nbuf ^= 1;
    }
}

// ---------------------------------------------------------------------------
// Edge scatter: FOUR edges per warp (two per 16-lane half, unrolled x2 for
// memory-level parallelism). Per edge: 16 lanes x (LDG.128 + RED v4.f16x2).
// Both edges' loads issue before the first reduction -> MLP=2 per lane.
// ---------------------------------------------------------------------------
__global__ void scatter_kernel(const int* __restrict__ esrc,
                               const int* __restrict__ edst,
                               const float* __restrict__ b_msg, int n_edges) {
    int gwarp = (blockIdx.x * blockDim.x + threadIdx.x) >> 5;
    int lane  = threadIdx.x & 31;
    int half  = lane >> 4;
    int hl    = lane & 15;
    int eA = gwarp * 4 + half;       // first edge of this half-warp
    int eB = eA + 2;                 // second edge (independent chain)
    if (eA >= n_edges) return;

    float4 b0 = *reinterpret_cast<const float4*>(b_msg + hl * 8);
    float4 b1 = *reinterpret_cast<const float4*>(b_msg + hl * 8 + 4);
    float bb[8] = {b0.x, b0.y, b0.z, b0.w, b1.x, b1.y, b1.z, b1.w};

    bool hasB = (eB < n_edges);
    int sA = esrc[eA], dA = edst[eA];
    int sB = hasB ? esrc[eB] : sA;
    int dB = hasB ? edst[eB] : dA;

    // Issue both T-row loads up front (independent latency chains)
    uint4 tA = *reinterpret_cast<const uint4*>(
        g_Th + (size_t)sA * DIM_H + hl * 8);
    uint4 tB = *reinterpret_cast<const uint4*>(
        g_Th + (size_t)sB * DIM_H + hl * 8);

    uint32_t twA[4] = {tA.x, tA.y, tA.z, tA.w};
    uint32_t rA[4];
#pragma unroll
    for (int j = 0; j < 4; j++) {
        __half2 h = *reinterpret_cast<__half2*>(&twA[j]);
        float2 f = __half22float2(h);
        __half2 o = __floats2half2_rn(f.x + bb[2 * j], f.y + bb[2 * j + 1]);
        rA[j] = *reinterpret_cast<uint32_t*>(&o);
    }
    __half* pA = g_msg + (size_t)dA * DIM_H + hl * 8;
    asm volatile("red.global.add.noftz.v4.f16x2 [%0], {%1, %2, %3, %4};"
                 :: "l"(pA), "r"(rA[0]), "r"(rA[1]), "r"(rA[2]), "r"(rA[3])
                 : "memory");

    if (hasB) {
        uint32_t twB[4] = {tB.x, tB.y, tB.z, tB.w};
        uint32_t rB[4];
#pragma unroll
        for (int j = 0; j < 4; j++) {
            __half2 h = *reinterpret_cast<__half2*>(&twB[j]);
            float2 f = __half22float2(h);
            __half2 o = __floats2half2_rn(f.x + bb[2 * j], f.y + bb[2 * j + 1]);
            rB[j] = *reinterpret_cast<uint32_t*>(&o);
        }
        __half* pB = g_msg + (size_t)dB * DIM_H + hl * 8;
        asm volatile("red.global.add.noftz.v4.f16x2 [%0], {%1, %2, %3, %4};"
                     :: "l"(pB), "r"(rB[0]), "r"(rB[1]), "r"(rB[2]), "r"(rB[3])
                     : "memory");
    }
}

// ---------------------------------------------------------------------------
// Fused GRU gates + LayerNorm + message residual. One warp per node.
// Re-zeroes g_colsum for the next graph replay (block 0).
// ---------------------------------------------------------------------------
__device__ __forceinline__ float sigmoidf_(float x) {
    return 1.0f / (1.0f + expf(-x));
}

__global__ void gru_ln_kernel(const float* __restrict__ nodes,
                              const float* __restrict__ gamma,
                              const float* __restrict__ beta,
                              float* __restrict__ out, int n_nodes) {
    if (blockIdx.x == 0 && threadIdx.x < DIM_H)
        g_colsum[threadIdx.x] = 0.f;

    int gwarp = (blockIdx.x * blockDim.x + threadIdx.x) >> 5;
    int lane  = threadIdx.x & 31;
    if (gwarp >= n_nodes) return;

    size_t base = (size_t)gwarp * DIM_H;
    size_t gb   = (size_t)gwarp * DIM_3H;
    int le = lane * 4;

    float4 h4 = reinterpret_cast<const float4*>(nodes + base)[lane];

    float mm[4], ir[4], iz[4], in_[4], hr[4], hz[4], hn[4];
    ld4h(g_msg + base + le, mm);
    ld4h(g_gih + gb + le, ir);
    ld4h(g_gih + gb + 128 + le, iz);
    ld4h(g_gih + gb + 256 + le, in_);
    ld4h(g_ghh + gb + le, hr);
    ld4h(g_ghh + gb + 128 + le, hz);
    ld4h(g_ghh + gb + 256 + le, hn);

    float hh[4] = {h4.x, h4.y, h4.z, h4.w};

    float hx[4];
    float s = 0.f, s2 = 0.f;
#pragma unroll
    for (int c = 0; c < 4; c++) {
        float r = sigmoidf_(ir[c] + hr[c]);
        float z = sigmoidf_(iz[c] + hz[c]);
        float n = tanhf(in_[c] + r * hn[c]);
        hx[c] = (1.0f - z) * n + z * hh[c];
        s  += hx[c];
        s2 += hx[c] * hx[c];
    }
#pragma unroll
    for (int off = 16; off > 0; off >>= 1) {
        s  += __shfl_xor_sync(0xFFFFFFFF, s,  off);
        s2 += __shfl_xor_sync(0xFFFFFFFF, s2, off);
    }
    float mu   = s  * (1.0f / DIM_H);
    float var  = s2 * (1.0f / DIM_H) - mu * mu;
    float rstd = rsqrtf(var + LN_EPS);

    float4 g4 = reinterpret_cast<const float4*>(gamma)[lane];
    float4 b4 = reinterpret_cast<const float4*>(beta)[lane];
    float gg[4] = {g4.x, g4.y, g4.z, g4.w};
    float bb[4] = {b4.x, b4.y, b4.z, b4.w};

    float o[4];
#pragma unroll
    for (int c = 0; c < 4; c++)
        o[c] = gg[c] * (hx[c] - mu) * rstd + bb[c] + mm[c];

    reinterpret_cast<float4*>(out + base)[lane] =
        make_float4(o[0], o[1], o[2], o[3]);
}

// ---------------------------------------------------------------------------
// Launch. Graph (round-11 structure):
//   main: prep -> gemmT -> scatter -> [wait evB] gemm2 -> [wait evJoin] gru_ln
//   s2:   [wait evFork] bias2 (evB) -> gemmGH (evJoin)
// ---------------------------------------------------------------------------
extern "C" void kernel_launch(void* const* d_in, const int* in_sizes, int n_in,
                              void* d_out, int out_size) {
    const float* nodes = (const float*)d_in[0];
    const float* W_msg = (const float*)d_in[1];
    const float* b_msg = (const float*)d_in[2];
    const float* w_ih  = (const float*)d_in[3];
    const float* w_hh  = (const float*)d_in[4];
    const float* b_ih  = (const float*)d_in[5];
    const float* b_hh  = (const float*)d_in[6];
    const float* gamma = (const float*)d_in[7];
    const float* beta  = (const float*)d_in[8];
    const int*   esrc  = (const int*)d_in[9];
    const int*   edst  = (const int*)d_in[10];
    float* out = (float*)d_out;

    int n_nodes = in_sizes[0] / DIM_H;
    int n_edges = in_sizes[9];

    float *pBias2;
    __half *pMsg, *pTh, *pGhh, *pGih, *pNh, *pWc, *pWi;
    cudaGetSymbolAddress((void**)&pBias2, g_bias2);
    cudaGetSymbolAddress((void**)&pMsg, g_msg);
    cudaGetSymbolAddress((void**)&pTh,  g_Th);
    cudaGetSymbolAddress((void**)&pGhh, g_ghh);
    cudaGetSymbolAddress((void**)&pGih, g_gih);
    cudaGetSymbolAddress((void**)&pNh,  g_nh);
    cudaGetSymbolAddress((void**)&pWc,  g_Wcat);
    cudaGetSymbolAddress((void**)&pWi,  g_Wih);

    cudaFuncSetAttribute(gemm_ws,
                         cudaFuncAttributeMaxDynamicSharedMemorySize, SM_TOTAL);

    static cudaStream_t s2 = nullptr;
    static cudaEvent_t evFork = nullptr, evB = nullptr, evJoin = nullptr;
    if (s2 == nullptr) {
        cudaStreamCreateWithFlags(&s2, cudaStreamNonBlocking);
        cudaEventCreateWithFlags(&evFork, cudaEventDisableTiming);
        cudaEventCreateWithFlags(&evB, cudaEventDisableTiming);
        cudaEventCreateWithFlags(&evJoin, cudaEventDisableTiming);
    }

    int nrt = (n_nodes + 127) / 128;
    int n8 = n_nodes * DIM_H / 8;
    int nbN = (n8 + 255) / 256;
    int nbW = 56;  // 14336 / 256

    // 1: fused prep (weights + nodes convert + msg zero + colsum)
    prep_kernel<<<nbN + nbW, 256>>>(nodes, W_msg, w_hh, w_ih, n8, nbN);

    // Fork side stream: bias2 then gemmGH
    cudaEventRecord(evFork, 0);
    cudaStreamWaitEvent(s2, evFork, 0);
    bias2_fast<<<12, 1024, 0, s2>>>(w_ih, b_ih, n_nodes);
    cudaEventRecord(evB, s2);
    gemm_ws<<<dim3(3, 49), 512, SM_TOTAL, s2>>>(
        pNh, pWc + 128 * DIM_H, b_hh, b_hh + 128,
        pGhh, DIM_3H, pGhh + 128, DIM_3H, n_nodes, nrt, 49);
    cudaEventRecord(evJoin, s2);

    // Main: T = nodes @ W_msg^T (one wave)
    gemm_ws<<<dim3(1, 148), 512, SM_TOTAL>>>(pNh, pWc, nullptr, nullptr,
                                             pTh, DIM_H, pTh, DIM_H,
                                             n_nodes, nrt, 148);
    // messages[dst] += T[src] + b_msg   (4 edges/warp, MLP=2 per lane)
    scatter_kernel<<<((n_edges + 3) / 4 * 32 + 255) / 256, 256>>>(
        esrc, edst, b_msg, n_edges);

    // gi = msg @ w_ih^T + bias2  (needs bias2 from s2)
    cudaStreamWaitEvent(0, evB, 0);
    gemm_ws<<<dim3(3, 49), 512, SM_TOTAL>>>(pMsg, pWi, pBias2, pBias2 + 128,
                                            pGih, DIM_3H, pGih + 128, DIM_3H,
                                            n_nodes, nrt, 49);

    // gru_ln needs gh from s2
    cudaStreamWaitEvent(0, evJoin, 0);
    gru_ln_kernel<<<(n_nodes + 7) / 8, 256>>>(nodes, gamma, beta, out, n_nodes);
}